// round 3
// baseline (speedup 1.0000x reference)
#include <cuda_runtime.h>
#include <cuda_bf16.h>
#include <math.h>
#include <stdint.h>

#define HWD 36864
#define BD 4
#define QD 256
#define ED 128
#define NSPLIT 18
#define KS (HWD / NSPLIT)   // 2048
#define BK 64
#define KT (KS / BK)        // 32

// smem: 4 bf16 tiles (xw, p, tgt, sgm), each 128 rows x 128 bytes, double buffered
#define TILE_B     16384
#define BUF_STRIDE (4 * TILE_B)          // 65536
#define SMEM_TOTAL (2 * BUF_STRIDE)      // 131072

// ---------------- static scratch ----------------
__device__ __align__(16) float g_Pxw[(size_t)BD * NSPLIT * QD * ED];  // (xw)·tgt partials
__device__ __align__(16) float g_Pp [(size_t)BD * NSPLIT * QD * ED];  // p·seg partials
__device__ float g_negsum_p[BD * NSPLIT * QD];
__device__ float g_psum_p  [BD * NSPLIT * QD];
__device__ float g_segsum_p[BD * NSPLIT * ED];
__device__ int   g_nnz_p   [BD * NSPLIT * ED];
__device__ float g_negsum[BD * QD];
__device__ float g_psum  [BD * QD];
__device__ float g_segsum[BD * ED];
__device__ int   g_nnze  [BD * ED];
__device__ float g_nnzf  [BD];

// SW128 swizzle on byte offset within a tile (128B rows)
__device__ __forceinline__ uint32_t swz(int off) {
    return (uint32_t)(off ^ ((off >> 3) & 0x70));
}

__device__ __forceinline__ void sts_4bf16(uint32_t addr, float a, float b,
                                          float c, float d) {
    __nv_bfloat162 lo = __floats2bfloat162_rn(a, b);
    __nv_bfloat162 hi = __floats2bfloat162_rn(c, d);
    asm volatile("st.shared.v2.b32 [%0], {%1,%2};"
                 :: "r"(addr), "r"(*(uint32_t*)&lo), "r"(*(uint32_t*)&hi));
}

// ---------------- fused prep + 2x GEMM (mma.sync, split-K) ----------------
__global__ __launch_bounds__(256, 1) void fused_gemm_kernel(
    const float* __restrict__ ml, const float* __restrict__ pm,
    const float* __restrict__ pl, const float* __restrict__ seg)
{
    extern __shared__ char smem[];
    const uint32_t smem_base = (uint32_t)__cvta_generic_to_shared(smem);
    const int tid = threadIdx.x;
    const int wid = tid >> 5, lane = tid & 31;

    int bx = blockIdx.x;                 // 0..143
    const int split = bx % NSPLIT; bx /= NSPLIT;
    const int mt = bx & 1;         bx >>= 1;
    const int b = bx;

    // thread -> (row r0+16j, 4-float col group) mapping for transform
    const int r0 = tid >> 4;              // 0..15
    const int cby = (tid & 15) * 8;       // byte offset within 128B tile row
    const size_t koff0 = (size_t)split * KS + (tid & 15) * 4;
    const float* pml = ml + ((size_t)(b * QD + mt * 128 + r0)) * HWD + koff0;
    const float* ppm = pm + ((size_t)(b * QD + mt * 128 + r0)) * HWD + koff0;
    const float* ppl = pl + ((size_t)(b * QD + mt * 128 + r0)) * HWD + koff0;
    const float* psg = seg + ((size_t)(b * ED + r0)) * HWD + koff0;

    // warp layout for MMA: wm in {0,1} -> 64-row half, wn in {0..3} -> 32-col quarter
    const int wm = wid & 1;
    const int wn = wid >> 1;

    float acc1[4][4][4];   // xw · tgt
    float acc2[4][4][4];   // p  · seg
#pragma unroll
    for (int mi = 0; mi < 4; mi++)
#pragma unroll
        for (int ni = 0; ni < 4; ni++)
#pragma unroll
            for (int c = 0; c < 4; c++) { acc1[mi][ni][c] = 0.f; acc2[mi][ni][c] = 0.f; }

    float nl[8], plo[8], sl[8]; int zl[8];
#pragma unroll
    for (int j = 0; j < 8; j++) { nl[j] = plo[j] = sl[j] = 0.f; zl[j] = 0; }

    for (int kt = 0; kt < KT; kt++) {
        const uint32_t tb = smem_base + (kt & 1) * BUF_STRIDE;
        const uint32_t t_xw = tb, t_p = tb + TILE_B,
                       t_tgt = tb + 2 * TILE_B, t_sgm = tb + 3 * TILE_B;
        const size_t kk = (size_t)kt * BK;

        // ---- transform phase: fp32 LDG -> math -> bf16 STS (swizzled) ----
#pragma unroll
        for (int j = 0; j < 8; j++) {
            const size_t ro = (size_t)(16 * j) * HWD + kk;
            float4 M = *(const float4*)(pml + ro);
            float4 W = *(const float4*)(ppm + ro);
            float4 L = *(const float4*)(ppl + ro);
            float4 S = *(const float4*)(psg + ro);
            const int off = (r0 + 16 * j) * 128 + cby;
            const uint32_t sw = swz(off);

            const float* mm = (const float*)&M;
            const float* ww = (const float*)&W;
            const float* ll = (const float*)&L;
            const float* ss = (const float*)&S;

            float xw[4], qv[4], tv[4];
#pragma unroll
            for (int u = 0; u < 4; u++) {
                float x = mm[u], wt = ww[u];
                xw[u] = x * wt;
                // negsum row accum: softplus(x)*w
                nl[j] += (log1pf(__expf(-fabsf(x))) + fmaxf(x, 0.f)) * wt;
                // p = sigmoid(l)*w
                qv[u] = __fdividef(wt, 1.f + __expf(-ll[u]));
                plo[j] += qv[u];
                bool on = ss[u] > 0.f;
                tv[u] = on ? 1.f : 0.f;
                zl[j] += on ? 1 : 0;
                sl[j] += ss[u];
            }
            sts_4bf16(t_xw + sw, xw[0], xw[1], xw[2], xw[3]);
            sts_4bf16(t_p  + sw, qv[0], qv[1], qv[2], qv[3]);
            sts_4bf16(t_tgt + sw, tv[0], tv[1], tv[2], tv[3]);
            sts_4bf16(t_sgm + sw, ss[0], ss[1], ss[2], ss[3]);
        }
        __syncthreads();

        // ---- MMA phase on this buffer ----
#pragma unroll
        for (int s = 0; s < 4; s++) {
            const int kbyte = s * 32;
            unsigned af[4][4], bfr[4][2];
            // GEMM 1: xw (A) x tgt (B)
#pragma unroll
            for (int mi = 0; mi < 4; mi++) {
                int row = wm * 64 + mi * 16 + (lane & 15);
                uint32_t addr = t_xw + swz(row * 128 + kbyte + ((lane >> 4) << 4));
                asm volatile("ldmatrix.sync.aligned.m8n8.x4.shared.b16 {%0,%1,%2,%3},[%4];"
                             : "=r"(af[mi][0]), "=r"(af[mi][1]), "=r"(af[mi][2]), "=r"(af[mi][3])
                             : "r"(addr));
            }
#pragma unroll
            for (int ni = 0; ni < 4; ni++) {
                int l = lane & 15;
                int row = wn * 32 + ni * 8 + (l & 7);
                uint32_t addr = t_tgt + swz(row * 128 + kbyte + ((l >> 3) << 4));
                asm volatile("ldmatrix.sync.aligned.m8n8.x2.shared.b16 {%0,%1},[%2];"
                             : "=r"(bfr[ni][0]), "=r"(bfr[ni][1]) : "r"(addr));
            }
#pragma unroll
            for (int mi = 0; mi < 4; mi++)
#pragma unroll
                for (int ni = 0; ni < 4; ni++)
                    asm volatile(
                        "mma.sync.aligned.m16n8k16.row.col.f32.bf16.bf16.f32 "
                        "{%0,%1,%2,%3},{%4,%5,%6,%7},{%8,%9},{%0,%1,%2,%3};\n"
                        : "+f"(acc1[mi][ni][0]), "+f"(acc1[mi][ni][1]),
                          "+f"(acc1[mi][ni][2]), "+f"(acc1[mi][ni][3])
                        : "r"(af[mi][0]), "r"(af[mi][1]), "r"(af[mi][2]), "r"(af[mi][3]),
                          "r"(bfr[ni][0]), "r"(bfr[ni][1]));
            // GEMM 2: p (A) x seg (B)
#pragma unroll
            for (int mi = 0; mi < 4; mi++) {
                int row = wm * 64 + mi * 16 + (lane & 15);
                uint32_t addr = t_p + swz(row * 128 + kbyte + ((lane >> 4) << 4));
                asm volatile("ldmatrix.sync.aligned.m8n8.x4.shared.b16 {%0,%1,%2,%3},[%4];"
                             : "=r"(af[mi][0]), "=r"(af[mi][1]), "=r"(af[mi][2]), "=r"(af[mi][3])
                             : "r"(addr));
            }
#pragma unroll
            for (int ni = 0; ni < 4; ni++) {
                int l = lane & 15;
                int row = wn * 32 + ni * 8 + (l & 7);
                uint32_t addr = t_sgm + swz(row * 128 + kbyte + ((l >> 3) << 4));
                asm volatile("ldmatrix.sync.aligned.m8n8.x2.shared.b16 {%0,%1},[%2];"
                             : "=r"(bfr[ni][0]), "=r"(bfr[ni][1]) : "r"(addr));
            }
#pragma unroll
            for (int mi = 0; mi < 4; mi++)
#pragma unroll
                for (int ni = 0; ni < 4; ni++)
                    asm volatile(
                        "mma.sync.aligned.m16n8k16.row.col.f32.bf16.bf16.f32 "
                        "{%0,%1,%2,%3},{%4,%5,%6,%7},{%8,%9},{%0,%1,%2,%3};\n"
                        : "+f"(acc2[mi][ni][0]), "+f"(acc2[mi][ni][1]),
                          "+f"(acc2[mi][ni][2]), "+f"(acc2[mi][ni][3])
                        : "r"(af[mi][0]), "r"(af[mi][1]), "r"(af[mi][2]), "r"(af[mi][3]),
                          "r"(bfr[ni][0]), "r"(bfr[ni][1]));
        }
        // no trailing sync: next transform writes the OTHER buffer; the next
        // iteration's pre-MMA sync orders this MMA vs. the write-after-read.
    }

    // ---- row-sum partials (deterministic 16-lane butterfly) ----
#pragma unroll
    for (int j = 0; j < 8; j++) {
        float v = nl[j], w2 = plo[j];
#pragma unroll
        for (int o = 8; o; o >>= 1) {
            v  += __shfl_xor_sync(0xffffffffu, v, o);
            w2 += __shfl_xor_sync(0xffffffffu, w2, o);
        }
        if ((tid & 15) == 0) {
            int row = r0 + 16 * j;
            g_negsum_p[(b * NSPLIT + split) * QD + mt * 128 + row] = v;
            g_psum_p  [(b * NSPLIT + split) * QD + mt * 128 + row] = w2;
        }
    }
    if (mt == 0) {
#pragma unroll
        for (int j = 0; j < 8; j++) {
            float v = sl[j]; int z = zl[j];
#pragma unroll
            for (int o = 8; o; o >>= 1) {
                v += __shfl_xor_sync(0xffffffffu, v, o);
                z += __shfl_xor_sync(0xffffffffu, z, o);
            }
            if ((tid & 15) == 0) {
                int e = r0 + 16 * j;
                g_segsum_p[(b * NSPLIT + split) * ED + e] = v;
                g_nnz_p   [(b * NSPLIT + split) * ED + e] = z;
            }
        }
    }

    // ---- accumulators -> global partials ----
    const size_t pbase = ((size_t)(b * NSPLIT + split) * QD + mt * 128) * ED;
#pragma unroll
    for (int mi = 0; mi < 4; mi++) {
        int r = wm * 64 + mi * 16 + (lane >> 2);
#pragma unroll
        for (int ni = 0; ni < 4; ni++) {
            int cc = wn * 32 + ni * 8 + (lane & 3) * 2;
            *(float2*)&g_Pxw[pbase + (size_t)r * ED + cc] =
                make_float2(acc1[mi][ni][0], acc1[mi][ni][1]);
            *(float2*)&g_Pxw[pbase + (size_t)(r + 8) * ED + cc] =
                make_float2(acc1[mi][ni][2], acc1[mi][ni][3]);
            *(float2*)&g_Pp[pbase + (size_t)r * ED + cc] =
                make_float2(acc2[mi][ni][0], acc2[mi][ni][1]);
            *(float2*)&g_Pp[pbase + (size_t)(r + 8) * ED + cc] =
                make_float2(acc2[mi][ni][2], acc2[mi][ni][3]);
        }
    }
}

// ---------------- sum reductions over splits ----------------
__global__ __launch_bounds__(256) void reduce_sums_kernel()
{
    int idx = blockIdx.x * 256 + threadIdx.x;   // 0..1535
    if (idx < BD * QD) {
        int b = idx >> 8, q = idx & 255;
        float a = 0.f, c = 0.f;
        for (int s = 0; s < NSPLIT; s++) {
            a += g_negsum_p[(b * NSPLIT + s) * QD + q];
            c += g_psum_p  [(b * NSPLIT + s) * QD + q];
        }
        g_negsum[idx] = a;
        g_psum[idx] = c;
    } else if (idx < BD * QD + BD * ED) {
        int k = idx - BD * QD;                  // 0..511
        int b = k >> 7, e = k & 127;
        float a = 0.f; int n = 0;
        for (int s = 0; s < NSPLIT; s++) {
            a += g_segsum_p[(b * NSPLIT + s) * ED + e];
            n += g_nnz_p   [(b * NSPLIT + s) * ED + e];
        }
        g_segsum[k] = a;
        g_nnze[k] = n;
    }
}

__global__ void nnz_final_kernel()
{
    int b = blockIdx.x;
    int v = g_nnze[b * ED + threadIdx.x];
#pragma unroll
    for (int o = 16; o; o >>= 1) v += __shfl_xor_sync(0xffffffffu, v, o);
    __shared__ int sm[4];
    if ((threadIdx.x & 31) == 0) sm[threadIdx.x >> 5] = v;
    __syncthreads();
    if (threadIdx.x == 0) g_nnzf[b] = (float)(sm[0] + sm[1] + sm[2] + sm[3]);
}

// ---------------- final cost assembly ----------------
__global__ __launch_bounds__(256) void epilogue_kernel(
    const float* __restrict__ positions, const float* __restrict__ true_positions,
    const float* __restrict__ iel, float* __restrict__ out)
{
    int idx = blockIdx.x * 256 + threadIdx.x;
    int e = idx & (ED - 1);
    int q = (idx >> 7) & (QD - 1);
    int b = idx >> 15;

    size_t poff = ((size_t)(b * NSPLIT) * QD + q) * ED + e;
    float gxw = 0.f, gd = 0.f;
#pragma unroll
    for (int s = 0; s < NSPLIT; s++) {
        size_t o = poff + (size_t)s * (QD * ED);
        gxw += g_Pxw[o];
        gd  += g_Pp[o];
    }

    // bce = (pos_qe + negsum - neg_qe)/nnz ; pos_qe - neg_qe = -(xw)·tgt
    float bce  = (g_negsum[b * QD + q] - gxw) / g_nnzf[b];
    float dice = 1.f - (2.f * gd + 1.f) /
                       (g_psum[b * QD + q] + g_segsum[b * ED + e] + 1.f);

    float x = iel[b * QD + q];
    float cls = log1pf(__expf(-fabsf(x))) + fmaxf(-x, 0.f);   // softplus(-x)

    float px = positions[(b * QD + q) * 2 + 0];
    float py = positions[(b * QD + q) * 2 + 1];
    float tx = true_positions[(b * ED + e) * 2 + 0];
    float ty = true_positions[(b * ED + e) * 2 + 1];
    float ax = fabsf(px - tx), ay = fabsf(py - ty);
    float hx = ax < 1.f ? 0.5f * ax * ax : ax - 0.5f;
    float hy = ay < 1.f ? 0.5f * ay * ay : ay - 0.5f;
    float dist = 0.5f * (hx + hy);

    out[idx] = cls + bce + dice + dist;
}

// ---------------- launch ----------------
extern "C" void kernel_launch(void* const* d_in, const int* in_sizes, int n_in,
                              void* d_out, int out_size)
{
    const float* mask_logits    = (const float*)d_in[0];
    const float* pred_mask      = (const float*)d_in[1];
    const float* portion_logits = (const float*)d_in[2];
    const float* segmap         = (const float*)d_in[3];
    const float* positions      = (const float*)d_in[4];
    const float* true_positions = (const float*)d_in[5];
    const float* iel            = (const float*)d_in[6];
    float* out = (float*)d_out;

    cudaFuncSetAttribute(fused_gemm_kernel,
                         cudaFuncAttributeMaxDynamicSharedMemorySize, SMEM_TOTAL);

    fused_gemm_kernel<<<BD * 2 * NSPLIT, 256, SMEM_TOTAL>>>(
        mask_logits, pred_mask, portion_logits, segmap);
    reduce_sums_kernel<<<6, 256>>>();
    nnz_final_kernel<<<BD, 128>>>();
    epilogue_kernel<<<(BD * QD * ED) / 256, 256>>>(positions, true_positions, iel, out);
}

// round 4
// speedup vs baseline: 3.5649x; 3.5649x over previous
#include <cuda_runtime.h>
#include <cuda_bf16.h>
#include <math.h>
#include <stdint.h>

#define HWD 36864
#define BD 4
#define QD 256
#define ED 128
#define NSPLIT 18
#define KS (HWD / NSPLIT)   // 2048
#define BK 32
#define KT (KS / BK)        // 64

// smem layout
#define STAGE_ARR 16384                  // 128 rows x 128B (32 fp32)
#define STAGE_B   (4 * STAGE_ARR)        // ml, pm, pl, seg  = 65536
#define TILE_BB   8192                   // 128 rows x 64B (32 bf16)
#define SM_TILES  (2 * STAGE_B)          // 131072
#define SMEM_TOTAL (SM_TILES + 4 * TILE_BB)   // 163840

// ---------------- static scratch ----------------
__device__ __align__(16) float g_Pxw[(size_t)BD * NSPLIT * QD * ED];
__device__ __align__(16) float g_Pp [(size_t)BD * NSPLIT * QD * ED];
__device__ float g_negsum_p[BD * NSPLIT * QD];
__device__ float g_psum_p  [BD * NSPLIT * QD];
__device__ float g_segsum_p[BD * NSPLIT * ED];
__device__ int   g_nnz_p   [BD * NSPLIT * ED];
__device__ float g_negsum[BD * QD];
__device__ float g_psum  [BD * QD];
__device__ float g_segsum[BD * ED];
__device__ int   g_nnze  [BD * ED];
__device__ float g_nnzf  [BD];

// SW64 swizzle for 64B-row bf16 tiles
__device__ __forceinline__ uint32_t swz64(int off) {
    return (uint32_t)(off ^ ((off >> 3) & 0x30));
}

__device__ __forceinline__ void sts_4bf16(uint32_t addr, float a, float b,
                                          float c, float d) {
    __nv_bfloat162 lo = __floats2bfloat162_rn(a, b);
    __nv_bfloat162 hi = __floats2bfloat162_rn(c, d);
    asm volatile("st.shared.v2.b32 [%0], {%1,%2};"
                 :: "r"(addr), "r"(*(uint32_t*)&lo), "r"(*(uint32_t*)&hi));
}

#define CPA16(dst, src) \
    asm volatile("cp.async.cg.shared.global [%0], [%1], 16;" :: "r"(dst), "l"(src))

// ---------------- fused prep + 2x GEMM (cp.async pipelined) ----------------
__global__ __launch_bounds__(256, 1) void fused_gemm_kernel(
    const float* __restrict__ ml, const float* __restrict__ pm,
    const float* __restrict__ pl, const float* __restrict__ seg)
{
    extern __shared__ __align__(16) char smem[];
    const uint32_t smem_base = (uint32_t)__cvta_generic_to_shared(smem);
    const int tid = threadIdx.x;
    const int wid = tid >> 5, lane = tid & 31;

    int bx = blockIdx.x;                 // 0..143
    const int split = bx % NSPLIT; bx /= NSPLIT;
    const int mt = bx & 1;         bx >>= 1;
    const int b = bx;

    // thread -> (row r0+32k, fp32 col group) mapping; same for cp.async and LDS
    const int r0 = tid >> 3;              // 0..31
    const int c8 = tid & 7;               // 16B group within 128B staging row
    const size_t colg = (size_t)split * KS + c8 * 4;   // + kt*BK at runtime

    const float* gml = ml + ((size_t)(b * QD + mt * 128)) * HWD + colg;
    const float* gpm = pm + ((size_t)(b * QD + mt * 128)) * HWD + colg;
    const float* gpl = pl + ((size_t)(b * QD + mt * 128)) * HWD + colg;
    const float* gsg = seg + ((size_t)(b * ED)) * HWD + colg;

    // warp layout for MMA
    const int wm = wid & 1;
    const int wn = wid >> 1;

    const uint32_t t_xw  = smem_base + SM_TILES;
    const uint32_t t_p   = t_xw + TILE_BB;
    const uint32_t t_tgt = t_xw + 2 * TILE_BB;
    const uint32_t t_sgm = t_xw + 3 * TILE_BB;

    float acc1[4][4][4];   // xw · tgt
    float acc2[4][4][4];   // p  · seg
#pragma unroll
    for (int mi = 0; mi < 4; mi++)
#pragma unroll
        for (int ni = 0; ni < 4; ni++)
#pragma unroll
            for (int c = 0; c < 4; c++) { acc1[mi][ni][c] = 0.f; acc2[mi][ni][c] = 0.f; }

    float nl[4], plo[4], sl[4]; int zl[4];
#pragma unroll
    for (int k = 0; k < 4; k++) { nl[k] = plo[k] = sl[k] = 0.f; zl[k] = 0; }

    // ---- cp.async issue for one iteration into one stage buffer ----
#define ISSUE_STAGE(kt_, buf_) do {                                            \
        const uint32_t sb = smem_base + (buf_) * STAGE_B;                      \
        const size_t kadv = (size_t)(kt_) * BK;                                \
        _Pragma("unroll")                                                      \
        for (int k_ = 0; k_ < 4; k_++) {                                       \
            const int row_ = r0 + 32 * k_;                                     \
            const uint32_t so = row_ * 128 + c8 * 16;                          \
            const size_t go = (size_t)row_ * HWD + kadv;                       \
            CPA16(sb + 0 * STAGE_ARR + so, gml + go);                          \
            CPA16(sb + 1 * STAGE_ARR + so, gpm + go);                          \
            CPA16(sb + 2 * STAGE_ARR + so, gpl + go);                          \
            CPA16(sb + 3 * STAGE_ARR + so, gsg + go);                          \
        }                                                                      \
        asm volatile("cp.async.commit_group;");                                \
    } while (0)

    ISSUE_STAGE(0, 0);
    ISSUE_STAGE(1, 1);

    for (int kt = 0; kt < KT; kt++) {
        asm volatile("cp.async.wait_group 1;" ::: "memory");
        __syncthreads();   // MMA(kt-1) done reading bf16 tiles before overwrite

        // ---- transform: LDS fp32 -> math -> STS bf16 (swizzled 64B rows) ----
        const uint32_t sb = smem_base + (kt & 1) * STAGE_B;
#pragma unroll
        for (int k = 0; k < 4; k++) {
            const int row = r0 + 32 * k;
            const uint32_t so = row * 128 + c8 * 16;
            float4 M = *(const float4*)(smem + (kt & 1) * STAGE_B + 0 * STAGE_ARR + so);
            float4 W = *(const float4*)(smem + (kt & 1) * STAGE_B + 1 * STAGE_ARR + so);
            float4 L = *(const float4*)(smem + (kt & 1) * STAGE_B + 2 * STAGE_ARR + so);
            float4 S = *(const float4*)(smem + (kt & 1) * STAGE_B + 3 * STAGE_ARR + so);
            (void)sb;

            const float* mm = (const float*)&M;
            const float* ww = (const float*)&W;
            const float* ll = (const float*)&L;
            const float* ss = (const float*)&S;
            float xw[4], qv[4], tv[4];
#pragma unroll
            for (int u = 0; u < 4; u++) {
                float x = mm[u], wt = ww[u];
                xw[u] = x * wt;
                nl[k] += (__logf(1.f + __expf(-fabsf(x))) + fmaxf(x, 0.f)) * wt;
                qv[u] = __fdividef(wt, 1.f + __expf(-ll[u]));
                plo[k] += qv[u];
                bool on = ss[u] > 0.f;
                tv[u] = on ? 1.f : 0.f;
                zl[k] += on ? 1 : 0;
                sl[k] += ss[u];
            }
            const uint32_t sw = swz64(row * 64 + c8 * 8);
            sts_4bf16(t_xw + sw, xw[0], xw[1], xw[2], xw[3]);
            sts_4bf16(t_p  + sw, qv[0], qv[1], qv[2], qv[3]);
            sts_4bf16(t_tgt + sw, tv[0], tv[1], tv[2], tv[3]);
            sts_4bf16(t_sgm + sw, ss[0], ss[1], ss[2], ss[3]);
        }
        __syncthreads();   // bf16 tiles visible

        // refill the stage we just consumed (runs in background through MMA)
        if (kt + 2 < KT) ISSUE_STAGE(kt + 2, kt & 1);
        else asm volatile("cp.async.commit_group;");  // keep group count aligned

        // ---- MMA phase ----
#pragma unroll
        for (int s = 0; s < 2; s++) {
            const int kbyte = s * 32;
            unsigned af[4][4], bfr[4][2];
#pragma unroll
            for (int mi = 0; mi < 4; mi++) {
                int row = wm * 64 + mi * 16 + (lane & 15);
                uint32_t addr = t_xw + swz64(row * 64 + kbyte + ((lane >> 4) << 4));
                asm volatile("ldmatrix.sync.aligned.m8n8.x4.shared.b16 {%0,%1,%2,%3},[%4];"
                             : "=r"(af[mi][0]), "=r"(af[mi][1]), "=r"(af[mi][2]), "=r"(af[mi][3])
                             : "r"(addr));
            }
#pragma unroll
            for (int ni = 0; ni < 4; ni++) {
                int l = lane & 15;
                int row = wn * 32 + ni * 8 + (l & 7);
                uint32_t addr = t_tgt + swz64(row * 64 + kbyte + ((l >> 3) << 4));
                asm volatile("ldmatrix.sync.aligned.m8n8.x2.shared.b16 {%0,%1},[%2];"
                             : "=r"(bfr[ni][0]), "=r"(bfr[ni][1]) : "r"(addr));
            }
#pragma unroll
            for (int mi = 0; mi < 4; mi++)
#pragma unroll
                for (int ni = 0; ni < 4; ni++)
                    asm volatile(
                        "mma.sync.aligned.m16n8k16.row.col.f32.bf16.bf16.f32 "
                        "{%0,%1,%2,%3},{%4,%5,%6,%7},{%8,%9},{%0,%1,%2,%3};\n"
                        : "+f"(acc1[mi][ni][0]), "+f"(acc1[mi][ni][1]),
                          "+f"(acc1[mi][ni][2]), "+f"(acc1[mi][ni][3])
                        : "r"(af[mi][0]), "r"(af[mi][1]), "r"(af[mi][2]), "r"(af[mi][3]),
                          "r"(bfr[ni][0]), "r"(bfr[ni][1]));
#pragma unroll
            for (int mi = 0; mi < 4; mi++) {
                int row = wm * 64 + mi * 16 + (lane & 15);
                uint32_t addr = t_p + swz64(row * 64 + kbyte + ((lane >> 4) << 4));
                asm volatile("ldmatrix.sync.aligned.m8n8.x4.shared.b16 {%0,%1,%2,%3},[%4];"
                             : "=r"(af[mi][0]), "=r"(af[mi][1]), "=r"(af[mi][2]), "=r"(af[mi][3])
                             : "r"(addr));
            }
#pragma unroll
            for (int ni = 0; ni < 4; ni++) {
                int l = lane & 15;
                int row = wn * 32 + ni * 8 + (l & 7);
                uint32_t addr = t_sgm + swz64(row * 64 + kbyte + ((l >> 3) << 4));
                asm volatile("ldmatrix.sync.aligned.m8n8.x2.shared.b16 {%0,%1},[%2];"
                             : "=r"(bfr[ni][0]), "=r"(bfr[ni][1]) : "r"(addr));
            }
#pragma unroll
            for (int mi = 0; mi < 4; mi++)
#pragma unroll
                for (int ni = 0; ni < 4; ni++)
                    asm volatile(
                        "mma.sync.aligned.m16n8k16.row.col.f32.bf16.bf16.f32 "
                        "{%0,%1,%2,%3},{%4,%5,%6,%7},{%8,%9},{%0,%1,%2,%3};\n"
                        : "+f"(acc2[mi][ni][0]), "+f"(acc2[mi][ni][1]),
                          "+f"(acc2[mi][ni][2]), "+f"(acc2[mi][ni][3])
                        : "r"(af[mi][0]), "r"(af[mi][1]), "r"(af[mi][2]), "r"(af[mi][3]),
                          "r"(bfr[ni][0]), "r"(bfr[ni][1]));
        }
    }
#undef ISSUE_STAGE

    // ---- row-sum partials: butterfly over the 8 threads sharing a row ----
#pragma unroll
    for (int k = 0; k < 4; k++) {
        float v = nl[k], w2 = plo[k];
#pragma unroll
        for (int o = 4; o; o >>= 1) {
            v  += __shfl_xor_sync(0xffffffffu, v, o);
            w2 += __shfl_xor_sync(0xffffffffu, w2, o);
        }
        if (c8 == 0) {
            int row = r0 + 32 * k;
            g_negsum_p[(b * NSPLIT + split) * QD + mt * 128 + row] = v;
            g_psum_p  [(b * NSPLIT + split) * QD + mt * 128 + row] = w2;
        }
    }
    if (mt == 0) {
#pragma unroll
        for (int k = 0; k < 4; k++) {
            float v = sl[k]; int z = zl[k];
#pragma unroll
            for (int o = 4; o; o >>= 1) {
                v += __shfl_xor_sync(0xffffffffu, v, o);
                z += __shfl_xor_sync(0xffffffffu, z, o);
            }
            if (c8 == 0) {
                int e = r0 + 32 * k;
                g_segsum_p[(b * NSPLIT + split) * ED + e] = v;
                g_nnz_p   [(b * NSPLIT + split) * ED + e] = z;
            }
        }
    }

    // ---- accumulators -> global partials ----
    const size_t pbase = ((size_t)(b * NSPLIT + split) * QD + mt * 128) * ED;
#pragma unroll
    for (int mi = 0; mi < 4; mi++) {
        int r = wm * 64 + mi * 16 + (lane >> 2);
#pragma unroll
        for (int ni = 0; ni < 4; ni++) {
            int cc = wn * 32 + ni * 8 + (lane & 3) * 2;
            *(float2*)&g_Pxw[pbase + (size_t)r * ED + cc] =
                make_float2(acc1[mi][ni][0], acc1[mi][ni][1]);
            *(float2*)&g_Pxw[pbase + (size_t)(r + 8) * ED + cc] =
                make_float2(acc1[mi][ni][2], acc1[mi][ni][3]);
            *(float2*)&g_Pp[pbase + (size_t)r * ED + cc] =
                make_float2(acc2[mi][ni][0], acc2[mi][ni][1]);
            *(float2*)&g_Pp[pbase + (size_t)(r + 8) * ED + cc] =
                make_float2(acc2[mi][ni][2], acc2[mi][ni][3]);
        }
    }
}

// ---------------- sum reductions over splits ----------------
__global__ __launch_bounds__(256) void reduce_sums_kernel()
{
    int idx = blockIdx.x * 256 + threadIdx.x;
    if (idx < BD * QD) {
        int b = idx >> 8, q = idx & 255;
        float a = 0.f, c = 0.f;
        for (int s = 0; s < NSPLIT; s++) {
            a += g_negsum_p[(b * NSPLIT + s) * QD + q];
            c += g_psum_p  [(b * NSPLIT + s) * QD + q];
        }
        g_negsum[idx] = a;
        g_psum[idx] = c;
    } else if (idx < BD * QD + BD * ED) {
        int k = idx - BD * QD;
        int b = k >> 7, e = k & 127;
        float a = 0.f; int n = 0;
        for (int s = 0; s < NSPLIT; s++) {
            a += g_segsum_p[(b * NSPLIT + s) * ED + e];
            n += g_nnz_p   [(b * NSPLIT + s) * ED + e];
        }
        g_segsum[k] = a;
        g_nnze[k] = n;
    }
}

__global__ void nnz_final_kernel()
{
    int b = blockIdx.x;
    int v = g_nnze[b * ED + threadIdx.x];
#pragma unroll
    for (int o = 16; o; o >>= 1) v += __shfl_xor_sync(0xffffffffu, v, o);
    __shared__ int sm[4];
    if ((threadIdx.x & 31) == 0) sm[threadIdx.x >> 5] = v;
    __syncthreads();
    if (threadIdx.x == 0) g_nnzf[b] = (float)(sm[0] + sm[1] + sm[2] + sm[3]);
}

// ---------------- final cost assembly ----------------
__global__ __launch_bounds__(256) void epilogue_kernel(
    const float* __restrict__ positions, const float* __restrict__ true_positions,
    const float* __restrict__ iel, float* __restrict__ out)
{
    int idx = blockIdx.x * 256 + threadIdx.x;
    int e = idx & (ED - 1);
    int q = (idx >> 7) & (QD - 1);
    int b = idx >> 15;

    size_t poff = ((size_t)(b * NSPLIT) * QD + q) * ED + e;
    float gxw = 0.f, gd = 0.f;
#pragma unroll
    for (int s = 0; s < NSPLIT; s++) {
        size_t o = poff + (size_t)s * (QD * ED);
        gxw += g_Pxw[o];
        gd  += g_Pp[o];
    }

    float bce  = (g_negsum[b * QD + q] - gxw) / g_nnzf[b];
    float dice = 1.f - (2.f * gd + 1.f) /
                       (g_psum[b * QD + q] + g_segsum[b * ED + e] + 1.f);

    float x = iel[b * QD + q];
    float cls = log1pf(__expf(-fabsf(x))) + fmaxf(-x, 0.f);

    float px = positions[(b * QD + q) * 2 + 0];
    float py = positions[(b * QD + q) * 2 + 1];
    float tx = true_positions[(b * ED + e) * 2 + 0];
    float ty = true_positions[(b * ED + e) * 2 + 1];
    float ax = fabsf(px - tx), ay = fabsf(py - ty);
    float hx = ax < 1.f ? 0.5f * ax * ax : ax - 0.5f;
    float hy = ay < 1.f ? 0.5f * ay * ay : ay - 0.5f;
    float dist = 0.5f * (hx + hy);

    out[idx] = cls + bce + dice + dist;
}

// ---------------- launch ----------------
extern "C" void kernel_launch(void* const* d_in, const int* in_sizes, int n_in,
                              void* d_out, int out_size)
{
    const float* mask_logits    = (const float*)d_in[0];
    const float* pred_mask      = (const float*)d_in[1];
    const float* portion_logits = (const float*)d_in[2];
    const float* segmap         = (const float*)d_in[3];
    const float* positions      = (const float*)d_in[4];
    const float* true_positions = (const float*)d_in[5];
    const float* iel            = (const float*)d_in[6];
    float* out = (float*)d_out;

    cudaFuncSetAttribute(fused_gemm_kernel,
                         cudaFuncAttributeMaxDynamicSharedMemorySize, SMEM_TOTAL);

    fused_gemm_kernel<<<BD * 2 * NSPLIT, 256, SMEM_TOTAL>>>(
        mask_logits, pred_mask, portion_logits, segmap);
    reduce_sums_kernel<<<6, 256>>>();
    nnz_final_kernel<<<BD, 128>>>();
    epilogue_kernel<<<(BD * QD * ED) / 256, 256>>>(positions, true_positions, iel, out);
}